// round 2
// baseline (speedup 1.0000x reference)
#include <cuda_runtime.h>

// Not-a-knot cubic spline upsample, B x 8192 fp32 -> B x (8192*ups).
// Tridiagonal [1,4,1] inverse is an exponential Green's function (lam = sqrt(3)-2),
// composed with the 6*[1,-2,1] rhs stencil into ONE symmetric FIR on y directly:
//   M[i] = sum_k c_k y[i+k],  c_0 = 2*sqrt(3)*(lam-1),  c_k = sqrt(3)(1-lam)^2 lam^{k-1}
// Truncated at K=8 taps (error ~1e-4 absolute on M -> ~2e-5 on output).
// M is therefore LOCAL -> tile each row across 8 CTAs with a 12-element halo.
// Boundary-image corrections + not-a-knot end formulas handled by 20 edge
// threads in the first/last tile of each row.

#define W_DIM  8192
#define NTHR   256
#define TILE_Q 4096
#define KT     8
#define NYMAX  1088

#define LAM   (-0.26794919243112270647f)   // sqrt(3) - 2
#define ACOEF (0.28867513459481288225f)    // 1 / (2*sqrt(3))

__device__ __forceinline__ float lam_pow(int e) {
    float p = 1.0f;
    for (int s = 0; s < e; ++s) p *= LAM;
    return p;
}

__global__ __launch_bounds__(NTHR, 5)
void spline_kernel(const float* __restrict__ x, float* __restrict__ out,
                   int nout, float step) {
    __shared__ float sy[NYMAX];
    __shared__ float sM[NYMAX];

    const int tid = threadIdx.x;
    const int row = blockIdx.y;
    const int qbase = blockIdx.x * TILE_Q;
    const int n = W_DIM - 4;

    const float* xr = x + (size_t)row * W_DIM;
    float* outr = out + (size_t)row * nout + qbase;

    // ---- tile geometry (all threads compute identically) ----
    int imin = (int)((float)qbase * step) - 2; if (imin < 0) imin = 0;
    int imax = (int)((float)(qbase + TILE_Q - 1) * step) + 2;
    if (imax > W_DIM - 2) imax = W_DIM - 2;
    int ilo = imin - 12; if (ilo < 0) ilo = 0; ilo &= ~3;
    int ihi = (imax + 14 + 3) & ~3; if (ihi > W_DIM) ihi = W_DIM;
    const int NY = ihi - ilo;

    // ---- load y slice (+halo), float4, aligned (ilo % 4 == 0) ----
    {
        const float4* x4 = (const float4*)(xr + ilo);
        float4* sy4 = (float4*)sy;
        for (int v = tid; v < (NY >> 2); v += NTHR) sy4[v] = x4[v];
    }
    __syncthreads();

    // ---- interior M via 17-tap symmetric FIR on y ----
    {
        const float C0 = -4.3923048f;
        const float C[KT] = { 2.7846097f, -0.7461340f, 0.1999261f, -0.0535701f,
                              0.0143541f, -0.0038462f, 0.0010306f, -0.0002761f };
        const int nchunk = (NY - 24) >> 2;
        for (int c = tid; c < nchunk; c += NTHR) {
            const int li0 = 12 + 4 * c;           // li0 % 4 == 0
            float win[20];                         // y[li0-8 .. li0+11]
            const float4* wsrc = (const float4*)(sy + li0 - 8);
            #pragma unroll
            for (int v = 0; v < 5; ++v) ((float4*)win)[v] = wsrc[v];
            const int gi0 = ilo + li0;
            #pragma unroll
            for (int m = 0; m < 4; ++m) {
                float acc = C0 * win[8 + m];
                #pragma unroll
                for (int k = 1; k <= KT; ++k)
                    acc = fmaf(C[k - 1], win[8 + m - k] + win[8 + m + k], acc);
                const int gi = gi0 + m;
                if (gi >= 20 && gi < W_DIM - 20) sM[li0 + m] = acc;
            }
        }
    }

    // ---- left edge: global M[0..19] (only the tile containing y[0]) ----
    if (ilo == 0 && tid < 20) {
        const float M1 = sy[2] - 2.f * sy[1] + sy[0];
        float SL = 0.f, lp = LAM;
        for (int mm = 0; mm < 24; ++mm) {
            float b = 6.f * (sy[mm + 3] - 2.f * sy[mm + 2] + sy[mm + 1]);
            if (mm == 0) b -= M1;
            SL = fmaf(lp, b, SL);
            lp *= LAM;
        }
        float Mv;
        if (tid == 1) {
            Mv = M1;
        } else {
            const int jj = (tid == 0) ? 0 : tid - 2;   // tid==0 needs M[2]
            float acc = 0.f;
            for (int k = -12; k <= 12; ++k) {
                const int j = jj + k;
                if (j < 0) continue;                    // j < n always here
                float b = 6.f * (sy[j + 3] - 2.f * sy[j + 2] + sy[j + 1]);
                if (j == 0) b -= M1;
                acc = fmaf(lam_pow(k < 0 ? -k : k), b, acc);
            }
            acc -= lam_pow(jj + 1) * SL;
            Mv = ACOEF * acc;
            if (tid == 0) Mv = 2.f * M1 - Mv;           // M[0] = 2*M1 - M[2]
        }
        sM[tid] = Mv;
    }

    // ---- right edge: global M[W-20..W-1] (only the tile containing y[W-1]) ----
    if (ihi == W_DIM && tid >= 32 && tid < 52) {
        const int t = tid - 32;
        const int i = W_DIM - 20 + t;
        const int lW = W_DIM - ilo;
        const float Mn2 = sy[lW - 1] - 2.f * sy[lW - 2] + sy[lW - 3];
        float SR = 0.f, lp = LAM;
        for (int mm = 0; mm < 24; ++mm) {
            const int j = n - 1 - mm;
            float b = 6.f * (sy[j + 3 - ilo] - 2.f * sy[j + 2 - ilo] + sy[j + 1 - ilo]);
            if (j == n - 1) b -= Mn2;
            SR = fmaf(lp, b, SR);
            lp *= LAM;
        }
        float Mv;
        if (t == 18) {
            Mv = Mn2;                                   // i == W-2
        } else {
            const int jj = (t == 19) ? (n - 1) : (i - 2);  // t==19 needs M[W-3]
            float acc = 0.f;
            for (int k = -12; k <= 12; ++k) {
                const int j = jj + k;
                if (j >= n) continue;                   // j >= 0 always here
                float b = 6.f * (sy[j + 3 - ilo] - 2.f * sy[j + 2 - ilo] + sy[j + 1 - ilo]);
                if (j == n - 1) b -= Mn2;
                acc = fmaf(lam_pow(k < 0 ? -k : k), b, acc);
            }
            acc -= lam_pow(n - jj) * SR;
            Mv = ACOEF * acc;
            if (t == 19) Mv = 2.f * Mn2 - Mv;           // M[W-1] = 2*Mn2 - M[W-3]
        }
        sM[i - ilo] = Mv;
    }
    __syncthreads();

    // ---- evaluate outputs, float4 coalesced stores ----
    {
        float4* out4 = (float4*)outr;
        for (int qo = 4 * tid; qo < TILE_Q; qo += 4 * NTHR) {
            if (qbase + qo >= nout) break;
            float4 r;
            #pragma unroll
            for (int m = 0; m < 4; ++m) {
                const float fq = (float)(qbase + qo + m) * step;
                int i = (int)fq; if (i > W_DIM - 2) i = W_DIM - 2;
                const float tt = fq - (float)i;
                const int li = i - ilo;
                const float y0 = sy[li], y1 = sy[li + 1];
                const float m0 = sM[li], m1 = sM[li + 1];
                const float dy = y1 - y0;
                const float bb = fmaf(fmaf(2.f, m0, m1), -(1.f / 6.f), dy);
                const float cc2 = 0.5f * m0;
                const float cc3 = (m1 - m0) * (1.f / 6.f);
                ((float*)&r)[m] = fmaf(tt, fmaf(tt, fmaf(tt, cc3, cc2), bb), y0);
            }
            out4[qo >> 2] = r;
        }
    }
}

extern "C" void kernel_launch(void* const* d_in, const int* in_sizes, int n_in,
                              void* d_out, int out_size) {
    const float* x = (const float*)d_in[0];
    float* out = (float*)d_out;

    const int B = in_sizes[0] / W_DIM;                 // 512
    const int nout = out_size / B;                     // 32768
    const float step = (float)((double)(W_DIM - 1) / (double)(nout - 1));

    dim3 grid((nout + TILE_Q - 1) / TILE_Q, B);        // 8 x 512 = 4096 CTAs
    spline_kernel<<<grid, NTHR>>>(x, out, nout, step);
}

// round 3
// speedup vs baseline: 1.1902x; 1.1902x over previous
#include <cuda_runtime.h>

// Not-a-knot cubic spline upsample, B x 8192 fp32 -> B x (8192*ups).
// [1,4,1] tridiagonal inverse = exponential Green's function (lam = sqrt(3)-2),
// composed with the 6*[1,-2,1] rhs into a 17-tap FIR on y -> M is LOCAL.
// Per-tile: load y slice -> FIR M -> build per-interval cubic coefficient
// float4 table -> evaluate outputs with 1 LDS.128 + 3 FMA per point.
// Boundary images / not-a-knot ends handled by 20+20 threads in edge tiles
// using running-power sweeps (no nested power loops).

#define W_DIM  8192
#define NTHR   256
#define TILE_Q 4096
#define KT     8
#define NYMAX  1088
#define SCMAX  1040

#define LAM   (-0.26794919243112270647f)   // sqrt(3) - 2
#define ACOEF (0.28867513459481288225f)    // 1 / (2*sqrt(3))

__global__ __launch_bounds__(NTHR, 4)
void spline_kernel(const float* __restrict__ x, float* __restrict__ out,
                   int nout, float step) {
    __shared__ float  sy[NYMAX];
    __shared__ float  sM[NYMAX];
    __shared__ float4 sC[SCMAX];

    const int tid = threadIdx.x;
    const int row = blockIdx.y;
    const int qbase = blockIdx.x * TILE_Q;
    const int n = W_DIM - 4;

    const float* xr = x + (size_t)row * W_DIM;
    float* outr = out + (size_t)row * nout + qbase;

    // ---- tile geometry (identical fp expressions to the eval phase) ----
    int imin = (int)((float)qbase * step);
    int imax = (int)((float)(qbase + TILE_Q - 1) * step);
    if (imax > W_DIM - 2) imax = W_DIM - 2;
    int ilo = imin - 12; if (ilo < 0) ilo = 0; ilo &= ~3;
    int ihi = (imax + 17) & ~3; if (ihi > W_DIM) ihi = W_DIM;
    const int NY = ihi - ilo;

    // ---- load y slice (+halo), aligned float4 ----
    {
        const float4* x4 = (const float4*)(xr + ilo);
        float4* sy4 = (float4*)sy;
        for (int v = tid; v < (NY >> 2); v += NTHR) sy4[v] = x4[v];
    }
    __syncthreads();

    // ---- interior M via 17-tap symmetric FIR on y ----
    {
        const float C0 = -4.3923048f;
        const float C[KT] = { 2.7846097f, -0.7461340f, 0.1999261f, -0.0535701f,
                              0.0143541f, -0.0038462f, 0.0010306f, -0.0002761f };
        const int nchunk = (NY - 24) >> 2;
        for (int c = tid; c < nchunk; c += NTHR) {
            const int li0 = 12 + 4 * c;
            float win[20];                          // y[li0-8 .. li0+11]
            const float4* wsrc = (const float4*)(sy + li0 - 8);
            #pragma unroll
            for (int v = 0; v < 5; ++v) ((float4*)win)[v] = wsrc[v];
            const int gi0 = ilo + li0;
            #pragma unroll
            for (int m = 0; m < 4; ++m) {
                float acc = C0 * win[8 + m];
                #pragma unroll
                for (int k = 1; k <= KT; ++k)
                    acc = fmaf(C[k - 1], win[8 + m - k] + win[8 + m + k], acc);
                const int gi = gi0 + m;
                if (gi >= 20 && gi < W_DIM - 20) sM[li0 + m] = acc;
            }
        }
    }

    // ---- left edge: global M[0..19] (tile containing y[0] only) ----
    if (ilo == 0 && tid < 20) {
        const float M1 = sy[2] - 2.f * sy[1] + sy[0];
        // SL = sum_{j=0}^{23} lam^{j+1} b_j   (running power)
        float SL = 0.f, lp = LAM;
        #pragma unroll 4
        for (int j = 0; j < 24; ++j) {
            float b = 6.f * (sy[j + 3] - 2.f * sy[j + 2] + sy[j + 1]);
            if (j == 0) b -= M1;
            SL = fmaf(lp, b, SL);
            lp *= LAM;
        }
        float Mv;
        if (tid == 1) {
            Mv = M1;
        } else {
            const int jj = (tid == 0) ? 0 : tid - 2;
            float acc = 0.f, p = 1.f;
            #pragma unroll 4
            for (int d = 0; d <= 12; ++d) {        // j = jj-d
                const int j = jj - d;
                if (j >= 0) {
                    float b = 6.f * (sy[j + 3] - 2.f * sy[j + 2] + sy[j + 1]);
                    if (j == 0) b -= M1;
                    acc = fmaf(p, b, acc);
                }
                p *= LAM;
            }
            p = LAM;
            #pragma unroll 4
            for (int d = 1; d <= 12; ++d) {        // j = jj+d  (always < n here)
                const int j = jj + d;
                float b = 6.f * (sy[j + 3] - 2.f * sy[j + 2] + sy[j + 1]);
                acc = fmaf(p, b, acc);
                p *= LAM;
            }
            float pw = LAM;                        // lam^{jj+1}
            for (int s = 0; s < jj; ++s) pw *= LAM;
            acc -= pw * SL;
            Mv = ACOEF * acc;
            if (tid == 0) Mv = 2.f * M1 - Mv;      // M[0] = 2*M1 - Mi[0]
        }
        sM[tid] = Mv;
    }

    // ---- right edge: global M[W-20..W-1] (tile containing y[W-1] only) ----
    if (ihi == W_DIM && tid >= 32 && tid < 52) {
        const int t = tid - 32;
        const int gi = W_DIM - 20 + t;
        const int lW = W_DIM - ilo;
        const float Mn2 = sy[lW - 1] - 2.f * sy[lW - 2] + sy[lW - 3];
        // SR = sum_{m=0}^{23} lam^{m+1} b_{n-1-m}
        float SR = 0.f, lp = LAM;
        #pragma unroll 4
        for (int m = 0; m < 24; ++m) {
            const int j = n - 1 - m;
            float b = 6.f * (sy[j + 3 - ilo] - 2.f * sy[j + 2 - ilo] + sy[j + 1 - ilo]);
            if (j == n - 1) b -= Mn2;
            SR = fmaf(lp, b, SR);
            lp *= LAM;
        }
        float Mv;
        if (t == 18) {
            Mv = Mn2;                              // gi == W-2
        } else {
            const int jj = (t == 19) ? (n - 1) : (gi - 2);
            float acc = 0.f, p = 1.f;
            #pragma unroll 4
            for (int d = 0; d <= 12; ++d) {        // j = jj-d (always >= 0 here)
                const int j = jj - d;
                float b = 6.f * (sy[j + 3 - ilo] - 2.f * sy[j + 2 - ilo] + sy[j + 1 - ilo]);
                if (j == n - 1) b -= Mn2;
                acc = fmaf(p, b, acc);
                p *= LAM;
            }
            p = LAM;
            #pragma unroll 4
            for (int d = 1; d <= 12; ++d) {        // j = jj+d
                const int j = jj + d;
                if (j < n) {
                    float b = 6.f * (sy[j + 3 - ilo] - 2.f * sy[j + 2 - ilo] + sy[j + 1 - ilo]);
                    acc = fmaf(p, b, acc);
                }
                p *= LAM;
            }
            float pw = LAM;                        // lam^{n-jj}
            for (int s = 0; s < n - jj - 1; ++s) pw *= LAM;
            acc -= pw * SR;
            Mv = ACOEF * acc;
            if (t == 19) Mv = 2.f * Mn2 - Mv;      // M[W-1] = 2*Mn2 - Mi[n-1]
        }
        sM[gi - ilo] = Mv;
    }
    __syncthreads();

    // ---- build per-interval cubic coefficients (float4) ----
    {
        const int cbase = imin - ilo;
        const int nint = imax - imin + 1;
        for (int t = tid; t < nint; t += NTHR) {
            const int li = cbase + t;
            const float y0 = sy[li], y1 = sy[li + 1];
            const float m0 = sM[li], m1 = sM[li + 1];
            float4 c;
            c.x = y0;
            c.y = fmaf(fmaf(2.f, m0, m1), -(1.f / 6.f), y1 - y0);
            c.z = 0.5f * m0;
            c.w = (m1 - m0) * (1.f / 6.f);
            sC[t] = c;
        }
    }
    __syncthreads();

    // ---- evaluate: 1 LDS.128 + f2i/i2f + 3 FMA per point ----
    {
        float4* out4 = (float4*)outr;
        for (int qo = 4 * tid; qo < TILE_Q; qo += 4 * NTHR) {
            const float fqb = (float)(qbase + qo);
            float4 r;
            #pragma unroll
            for (int m = 0; m < 4; ++m) {
                const float fq = (fqb + (float)m) * step;
                int i = (int)fq;
                if (i > W_DIM - 2) i = W_DIM - 2;
                const float tt = fq - (float)i;
                const float4 c = sC[i - imin];
                ((float*)&r)[m] =
                    fmaf(tt, fmaf(tt, fmaf(tt, c.w, c.z), c.y), c.x);
            }
            out4[qo >> 2] = r;
        }
    }
}

extern "C" void kernel_launch(void* const* d_in, const int* in_sizes, int n_in,
                              void* d_out, int out_size) {
    const float* x = (const float*)d_in[0];
    float* out = (float*)d_out;

    const int B = in_sizes[0] / W_DIM;                 // 512
    const int nout = out_size / B;                     // 32768
    const float step = (float)((double)(W_DIM - 1) / (double)(nout - 1));

    dim3 grid((nout + TILE_Q - 1) / TILE_Q, B);        // 8 x 512 = 4096 CTAs
    spline_kernel<<<grid, NTHR>>>(x, out, nout, step);
}